// round 2
// baseline (speedup 1.0000x reference)
#include <cuda_runtime.h>

// BinaryTree collocation probability:
//   x = W[v_j + 2^20 - 1]                       (leaf row, 128 fp32)
//   path[l] = ((u_k + 2^20) >> (20 - l)) - 1,   l = 0..20  (root -> leaf)
//   out = prod_l sigmoid( dot(W[path[l]], x) )
//
// Strategy: single CTA, 21 warps, warp w owns level w. Each lane loads one
// float4 of x and one float4 of its level's W row (all 22 row fetches overlap
// in one DRAM latency window), dot4 + warp shfl reduce, sigmoid on lane 0,
// block product by thread 0. Launch-latency-bound by construction.

#define DEPTH 20
#define NDIMS 128
#define NLEVELS (DEPTH + 1)   // 21
#define NWARPS NLEVELS
#define NTHREADS (NWARPS * 32) // 672

__global__ void __launch_bounds__(NTHREADS, 1)
binary_tree_kernel(const float* __restrict__ W,
                   const int* __restrict__ v_j_idx,
                   const int* __restrict__ u_k_idx,
                   float* __restrict__ out)
{
    __shared__ float s_sig[NWARPS];

    const int tid  = threadIdx.x;
    const int wid  = tid >> 5;
    const int lane = tid & 31;

    // Scalar index loads hit L2/DRAM once; broadcast within warp.
    const int v_j = __ldg(v_j_idx);
    const int u_k = __ldg(u_k_idx);

    const long long leaf_row = (long long)v_j + ((1 << DEPTH) - 1);
    // path node for this warp's level
    const int t        = u_k + (1 << DEPTH);            // tgt_idx + 1
    const int node     = (t >> (DEPTH - wid)) - 1;      // valid for wid <= DEPTH
    const long long wr = (long long)node * NDIMS;

    // Each lane handles 4 contiguous dims via float4 (rows are 512B-aligned).
    const float4* xv = (const float4*)(W + leaf_row * NDIMS);
    const float4* nv = (const float4*)(W + wr);

    // wid is always < NWARPS here (exactly 21 warps launched)
    float4 a = __ldg(&nv[lane]);
    float4 b = __ldg(&xv[lane]);

    float s = a.x * b.x + a.y * b.y + a.z * b.z + a.w * b.w;

    // Warp reduction
    #pragma unroll
    for (int off = 16; off > 0; off >>= 1)
        s += __shfl_xor_sync(0xFFFFFFFFu, s, off);

    if (lane == 0) {
        // sigmoid(s) = 1 / (1 + exp(-s))
        s_sig[wid] = 1.0f / (1.0f + __expf(-s));
    }
    __syncthreads();

    if (tid == 0) {
        float p = 1.0f;
        #pragma unroll
        for (int l = 0; l < NLEVELS; ++l)
            p *= s_sig[l];
        out[0] = p;
    }
}

extern "C" void kernel_launch(void* const* d_in, const int* in_sizes, int n_in,
                              void* d_out, int out_size)
{
    const float* W   = (const float*)d_in[0];
    const int*   vj  = (const int*)d_in[1];
    const int*   uk  = (const int*)d_in[2];
    float*       out = (float*)d_out;

    binary_tree_kernel<<<1, NTHREADS>>>(W, vj, uk, out);
}

// round 3
// speedup vs baseline: 1.0452x; 1.0452x over previous
#include <cuda_runtime.h>

// BinaryTree collocation probability — latency-optimized.
//   x = W[v_j + 2^20 - 1];  path[l] = ((u_k + 2^20) >> (20 - l)) - 1
//   out = prod_l sigmoid( dot(W[path[l]], x) )
//
// 21 warps, warp w owns level w. 8 active lanes/warp, each lane owns 4 float4
// (64B) of both rows -> 4 independent dot4 chains, 3-step shfl reduce.
// All byte offsets computed in 32-bit (max 2^30 < 2^32) to keep the
// idx->LDG address chain short. __fdividef avoids the IEEE-div Newton tail.

#define DEPTH 20
#define NLEVELS (DEPTH + 1)   // 21
#define NTHREADS (NLEVELS * 32) // 672

__global__ void __launch_bounds__(NTHREADS, 1)
binary_tree_kernel(const float* __restrict__ W,
                   const int* __restrict__ v_j_idx,
                   const int* __restrict__ u_k_idx,
                   float* __restrict__ out)
{
    __shared__ float s_sig[NLEVELS];

    const int tid  = threadIdx.x;
    const int wid  = tid >> 5;
    const int lane = tid & 31;

    // First instructions: idx loads (same addr per warp -> broadcast, one line each)
    const int v_j = __ldg(v_j_idx);
    const int u_k = __ldg(u_k_idx);

    if (lane < 8) {
        // 32-bit byte offsets: row * 512B. node < 2^21 -> offset < 2^30.
        const unsigned leaf_off_b = ((unsigned)v_j + ((1u << DEPTH) - 1u)) << 9;
        const int      t          = u_k + (1 << DEPTH);
        const unsigned node_off_b = (unsigned)((t >> (DEPTH - wid)) - 1) << 9;

        const char* base = (const char*)W;
        const float4* xv = (const float4*)(base + leaf_off_b) + lane * 4;
        const float4* nv = (const float4*)(base + node_off_b) + lane * 4;

        // 8 independent LDG.128 per thread-slice; all overlap in one latency window.
        float4 a0 = __ldg(nv + 0), b0 = __ldg(xv + 0);
        float4 a1 = __ldg(nv + 1), b1 = __ldg(xv + 1);
        float4 a2 = __ldg(nv + 2), b2 = __ldg(xv + 2);
        float4 a3 = __ldg(nv + 3), b3 = __ldg(xv + 3);

        // 4 independent dot4 chains, then 2-level tree add.
        float s0 = a0.x*b0.x + a0.y*b0.y + a0.z*b0.z + a0.w*b0.w;
        float s1 = a1.x*b1.x + a1.y*b1.y + a1.z*b1.z + a1.w*b1.w;
        float s2 = a2.x*b2.x + a2.y*b2.y + a2.z*b2.z + a2.w*b2.w;
        float s3 = a3.x*b3.x + a3.y*b3.y + a3.z*b3.z + a3.w*b3.w;
        float s  = (s0 + s1) + (s2 + s3);

        // 3-step shfl reduce over 8 lanes.
        s += __shfl_xor_sync(0xFFu, s, 4, 8);
        s += __shfl_xor_sync(0xFFu, s, 2, 8);
        s += __shfl_xor_sync(0xFFu, s, 1, 8);

        if (lane == 0) {
            // sigmoid via fast exp + fast reciprocal (err ~2^-21, fine for 1e-3 gate)
            s_sig[wid] = __fdividef(1.0f, 1.0f + __expf(-s));
        }
    }
    __syncthreads();

    if (tid == 0) {
        float p = 1.0f;
        #pragma unroll
        for (int l = 0; l < NLEVELS; ++l)
            p *= s_sig[l];
        out[0] = p;
    }
}

extern "C" void kernel_launch(void* const* d_in, const int* in_sizes, int n_in,
                              void* d_out, int out_size)
{
    const float* W   = (const float*)d_in[0];
    const int*   vj  = (const int*)d_in[1];
    const int*   uk  = (const int*)d_in[2];
    float*       out = (float*)d_out;

    binary_tree_kernel<<<1, NTHREADS>>>(W, vj, uk, out);
}